// round 12
// baseline (speedup 1.0000x reference)
#include <cuda_runtime.h>
#include <cuda_fp16.h>
#include <cstdint>
#include <math.h>

#define BB 4
#define NN 4096
#define DD 512

// ---------------- device scratch (allocation-free rule) ----------------
__device__ __half g_Eh[(size_t)BB * NN * NN];   // 134 MB, fp16
__device__ __half g_xh[(size_t)BB * NN * DD];
__device__ __half g_wth[DD * DD];               // w^T fp16
__device__ __half g_yth[(size_t)BB * DD * NN];  // y^T fp16 (B-operand layout)
__device__ float  g_s [BB * NN];
__device__ float  g_v [DD];                     // v = w @ a

// ---------------- PTX helpers ----------------
__device__ __forceinline__ uint32_t smem_u32(const void* p) {
    uint32_t a;
    asm("{ .reg .u64 t; cvta.to.shared.u64 t, %1; cvt.u32.u64 %0, t; }" : "=r"(a) : "l"(p));
    return a;
}
__device__ __forceinline__ void cp16(uint32_t smem_addr, const void* gptr) {
    asm volatile("cp.async.cg.shared.global [%0], [%1], 16;" :: "r"(smem_addr), "l"(gptr));
}
#define CP_COMMIT() asm volatile("cp.async.commit_group;" ::: "memory")
template <int N> __device__ __forceinline__ void cp_wait() {
    asm volatile("cp.async.wait_group %0;" :: "n"(N) : "memory");
}
__device__ __forceinline__ void ldsm4(uint32_t& r0, uint32_t& r1, uint32_t& r2, uint32_t& r3,
                                      uint32_t addr) {
    asm volatile("ldmatrix.sync.aligned.m8n8.x4.shared.b16 {%0,%1,%2,%3}, [%4];"
                 : "=r"(r0), "=r"(r1), "=r"(r2), "=r"(r3) : "r"(addr));
}
__device__ __forceinline__ void mma16816(float* c, const uint32_t* a, const uint32_t* b) {
    asm volatile(
        "mma.sync.aligned.m16n8k16.row.col.f32.f16.f16.f32 "
        "{%0,%1,%2,%3}, {%4,%5,%6,%7}, {%8,%9}, {%0,%1,%2,%3};"
        : "+f"(c[0]), "+f"(c[1]), "+f"(c[2]), "+f"(c[3])
        : "r"(a[0]), "r"(a[1]), "r"(a[2]), "r"(a[3]), "r"(b[0]), "r"(b[1]));
}

// ================= GEMM: C[M,N] = A[M,K] @ B[N,K]^T, fp16 1-MMA =================
// CTA 128x128, 128 threads (4 warps), warp tile 64x64, BK=64, 3 stages, 2 CTAs/SM.
// ROWB=144: 128B of k-data per row + 16B pad -> 8-row ldmatrix slots hit
// distinct 16B banks (r*144 mod 128 = r*16).
#define ROWB 144
#define ABYTES (128 * ROWB)                  // 18432 per matrix tile
#define MSTAGES 3
#define MSTAGE_BYTES (2 * ABYTES)            // 36864
#define GEMM_SMEM (MSTAGES * MSTAGE_BYTES)   // 110592

template <typename OutT>
__global__ void __launch_bounds__(128, 2) gemm_f16(
    const __half* __restrict__ A_, const __half* __restrict__ B_,
    OutT* __restrict__ C_,
    int K, int lda, int ldb, int ldc,
    long long sAz, long long sBz, long long sCz)
{
    extern __shared__ char smem[];
    const uint32_t sb = smem_u32(smem);
    const int tid  = threadIdx.x;
    const int wid  = tid >> 5;
    const int lane = tid & 31;
    const int bcol = blockIdx.x * 128;
    const int brow = blockIdx.y * 128;
    const __half* A = A_ + (size_t)blockIdx.z * sAz;
    const __half* B = B_ + (size_t)blockIdx.z * sBz;
    OutT* C = C_ + (size_t)blockIdx.z * sCz;

    const int m_base = (wid & 1) * 64;
    const int n_base = (wid >> 1) * 64;

    float acc[4][8][4];
#pragma unroll
    for (int t = 0; t < 4; t++)
#pragma unroll
        for (int n = 0; n < 8; n++)
#pragma unroll
            for (int j = 0; j < 4; j++) acc[t][n][j] = 0.f;

    const int NCH = K >> 6;                   // K chunks of 64

    auto load_chunk = [&](int c, int s) {
        const int k0 = c << 6;
        const uint32_t base = sb + s * MSTAGE_BYTES;
#pragma unroll
        for (int i = 0; i < 8; i++) {         // 128 rows x 8 x 16B per matrix
            int id = tid + (i << 7);          // 0..1023
            int r  = id >> 3;                 // row 0..127
            int ch = id & 7;                  // 16B chunk 0..7
            uint32_t so = r * ROWB + ch * 16;
            cp16(base + so,          A + (size_t)(brow + r) * lda + k0 + ch * 8);
            cp16(base + ABYTES + so, B + (size_t)(bcol + r) * ldb + k0 + ch * 8);
        }
    };

    const uint32_t aoff = (uint32_t)(m_base + (lane & 15)) * ROWB + (lane >> 4) * 16;
    const uint32_t boff = (uint32_t)(n_base + (lane & 7) + ((lane >> 4) << 3)) * ROWB
                        + ((lane >> 3) & 1) * 16;

    auto compute = [&](int s) {
        const uint32_t base = sb + s * MSTAGE_BYTES;
#pragma unroll
        for (int kk = 0; kk < 4; kk++) {      // four k16 steps per 64-chunk
            const uint32_t kb = kk * 32;      // 16 fp16 = 32 bytes
            uint32_t af[4][4], bf[4][4];
#pragma unroll
            for (int t = 0; t < 4; t++)
                ldsm4(af[t][0], af[t][1], af[t][2], af[t][3],
                      base + aoff + (uint32_t)t * (16 * ROWB) + kb);
#pragma unroll
            for (int p = 0; p < 4; p++)
                ldsm4(bf[p][0], bf[p][1], bf[p][2], bf[p][3],
                      base + ABYTES + boff + (uint32_t)p * (16 * ROWB) + kb);
#pragma unroll
            for (int t = 0; t < 4; t++)
#pragma unroll
                for (int n = 0; n < 8; n++)
                    mma16816(acc[t][n], af[t], &bf[n >> 1][(n & 1) * 2]);
        }
    };

#pragma unroll
    for (int p = 0; p < MSTAGES - 1; p++) {
        if (p < NCH) load_chunk(p, p);
        CP_COMMIT();
    }
    for (int c = 0; c < NCH; c++) {
        cp_wait<MSTAGES - 2>();
        __syncthreads();
        if (c + MSTAGES - 1 < NCH) load_chunk(c + MSTAGES - 1, (c + MSTAGES - 1) % MSTAGES);
        CP_COMMIT();
        compute(c % MSTAGES);
    }

    // epilogue
#pragma unroll
    for (int t = 0; t < 4; t++) {
        const int m0 = brow + m_base + t * 16 + (lane >> 2);
#pragma unroll
        for (int n = 0; n < 8; n++) {
            const int cn = bcol + n_base + n * 8 + (lane & 3) * 2;
            if constexpr (sizeof(OutT) == 4) {
                *(float2*)((float*)C + (size_t)m0 * ldc + cn) =
                    make_float2(acc[t][n][0], acc[t][n][1]);
                *(float2*)((float*)C + (size_t)(m0 + 8) * ldc + cn) =
                    make_float2(acc[t][n][2], acc[t][n][3]);
            } else {
                __half2 h0 = __floats2half2_rn(acc[t][n][0], acc[t][n][1]);
                __half2 h1 = __floats2half2_rn(acc[t][n][2], acc[t][n][3]);
                *(__half2*)((__half*)C + (size_t)m0 * ldc + cn)       = h0;
                *(__half2*)((__half*)C + (size_t)(m0 + 8) * ldc + cn) = h1;
            }
        }
    }
}

// ---------------- small kernels ----------------
// fused: x -> fp16 AND s[row] = dot(x[row], v) in fp32
__global__ void __launch_bounds__(128) split_s_k(const float* __restrict__ x) {
    const int row = blockIdx.x;
    float4 xv = ((const float4*)(x + (size_t)row * DD))[threadIdx.x];
    float4 vv = ((const float4*)g_v)[threadIdx.x];
    __half2 h01 = __floats2half2_rn(xv.x, xv.y);
    __half2 h23 = __floats2half2_rn(xv.z, xv.w);
    *(uint2*)(g_xh + (size_t)row * DD + threadIdx.x * 4) =
        make_uint2(*(uint32_t*)&h01, *(uint32_t*)&h23);
    float sum = xv.x * vv.x + xv.y * vv.y + xv.z * vv.z + xv.w * vv.w;
#pragma unroll
    for (int o = 16; o; o >>= 1) sum += __shfl_xor_sync(0xffffffffu, sum, o);
    __shared__ float red[4];
    if ((threadIdx.x & 31) == 0) red[threadIdx.x >> 5] = sum;
    __syncthreads();
    if (threadIdx.x == 0) g_s[row] = red[0] + red[1] + red[2] + red[3];
}

__global__ void __launch_bounds__(256) wt_k(const float* __restrict__ w) {
    int id = blockIdx.x * 256 + threadIdx.x;   // id = n*512 + k
    int n = id >> 9, k = id & 511;
    g_wth[id] = __float2half(w[k * DD + n]);   // wt[n][k] = w[k][n]
}

__global__ void __launch_bounds__(128) v_k(const float* __restrict__ w, const float* __restrict__ a) {
    int k = blockIdx.x;
    float sum = 0.f;
    for (int t = threadIdx.x; t < DD; t += 128) sum += w[k * DD + t] * a[t];
#pragma unroll
    for (int o = 16; o; o >>= 1) sum += __shfl_xor_sync(0xffffffffu, sum, o);
    __shared__ float red[4];
    if ((threadIdx.x & 31) == 0) red[threadIdx.x >> 5] = sum;
    __syncthreads();
    if (threadIdx.x == 0) g_v[k] = red[0] + red[1] + red[2] + red[3];
}

__global__ void __launch_bounds__(256) row_kernel(const float* __restrict__ A_shape) {
    const int row = blockIdx.x;             // b*NN + i
    const int b   = row >> 12;
    const float4* arow4 = (const float4*)(A_shape + (size_t)row * NN);
    const float4* srow4 = (const float4*)(g_s + (size_t)b * NN);
    const float  si   = g_s[row];

    __shared__ float Erow[NN];
    float deg = 0.f, R = 0.f;

#pragma unroll
    for (int q = 0; q < 4; q++) {
        int j4 = threadIdx.x + q * 256;
        float4 av = arow4[j4];
        float4 sv = srow4[j4];
        float e[4];
        float aa[4] = {av.x, av.y, av.z, av.w};
        float ss[4] = {sv.x, sv.y, sv.z, sv.w};
#pragma unroll
        for (int e2 = 0; e2 < 4; e2++) {
            float u  = (si + ss[e2]) * 0.125f;
            float eu = __expf(-2.f * fabsf(u));
            float tt = __fdividef(1.f - eu, 1.f + eu);
            tt = copysignf(tt, u);
            float Av = 8.f * tt;
            Av = (Av >= 0.f) ? Av : 0.1f * Av;
            e[e2] = __expf(Av) * aa[e2];
            deg += aa[e2]; R += e[e2];
        }
        ((float4*)Erow)[j4] = make_float4(e[0], e[1], e[2], e[3]);
    }
#pragma unroll
    for (int o = 16; o; o >>= 1) {
        deg += __shfl_xor_sync(0xffffffffu, deg, o);
        R   += __shfl_xor_sync(0xffffffffu, R, o);
    }
    __shared__ float wdeg[8], wR[8], s_scale;
    const int warp = threadIdx.x >> 5;
    if ((threadIdx.x & 31) == 0) { wdeg[warp] = deg; wR[warp] = R; }
    __syncthreads();
    if (threadIdx.x == 0) {
        float D = 0.f, Rt = 0.f;
#pragma unroll
        for (int w2 = 0; w2 < 8; w2++) { D += wdeg[w2]; Rt += wR[w2]; }
        s_scale = D / Rt;
    }
    __syncthreads();
    const float sc = s_scale;

    __half* eh = g_Eh + (size_t)row * NN;
#pragma unroll
    for (int q = 0; q < 4; q++) {
        int j4 = threadIdx.x + q * 256;
        float4 e4 = ((float4*)Erow)[j4];
        __half2 h01 = __floats2half2_rn(e4.x * sc, e4.y * sc);
        __half2 h23 = __floats2half2_rn(e4.z * sc, e4.w * sc);
        *(uint2*)(eh + j4 * 4) = make_uint2(*(uint32_t*)&h01, *(uint32_t*)&h23);
    }
}

// ---------------- launch ----------------
extern "C" void kernel_launch(void* const* d_in, const int* in_sizes, int n_in,
                              void* d_out, int out_size)
{
    const float* x       = (const float*)d_in[0];
    const float* A_shape = (const float*)d_in[1];
    const float* w       = (const float*)d_in[2];
    const float* a       = (const float*)d_in[3];
    float* out = (float*)d_out;

    __half *pxh, *pwth, *pyth, *pEh;
    cudaGetSymbolAddress((void**)&pxh,  g_xh);
    cudaGetSymbolAddress((void**)&pwth, g_wth);
    cudaGetSymbolAddress((void**)&pyth, g_yth);
    cudaGetSymbolAddress((void**)&pEh,  g_Eh);

    cudaFuncSetAttribute(gemm_f16<float>,  cudaFuncAttributeMaxDynamicSharedMemorySize, GEMM_SMEM);
    cudaFuncSetAttribute(gemm_f16<__half>, cudaFuncAttributeMaxDynamicSharedMemorySize, GEMM_SMEM);

    static cudaStream_t s1 = nullptr;
    static cudaEvent_t evFork = nullptr, evJoin = nullptr;
    if (s1 == nullptr) {
        cudaStreamCreateWithFlags(&s1, cudaStreamNonBlocking);
        cudaEventCreateWithFlags(&evFork, cudaEventDisableTiming);
        cudaEventCreateWithFlags(&evJoin, cudaEventDisableTiming);
    }

    wt_k<<<(DD * DD) / 256, 256>>>(w);
    v_k<<<DD, 128>>>(w, a);
    split_s_k<<<BB * NN, 128>>>(x);

    cudaEventRecord(evFork, 0);
    cudaStreamWaitEvent(s1, evFork, 0);

    row_kernel<<<BB * NN, 256, 0, s1>>>(A_shape);

    // y^T[b] = wt @ x[b]^T  (M=512, N=4096, K=512, 4 batches) -- fp16 output
    gemm_f16<__half><<<dim3(NN / 128, DD / 128, BB), 128, GEMM_SMEM>>>(
        pwth, pxh, pyth,
        DD, DD, DD, NN,
        0, (long long)NN * DD, (long long)DD * NN);

    cudaEventRecord(evJoin, s1);
    cudaStreamWaitEvent(0, evJoin, 0);

    // out[b] = E[b] @ (y^T[b])^T  (M=4096, N=512, K=4096, 4 batches) -- fp32 out
    gemm_f16<float><<<dim3(DD / 128, NN / 128, BB), 128, GEMM_SMEM>>>(
        pEh, pyth, out,
        NN, NN, NN, DD,
        (long long)NN * NN, (long long)DD * NN, (long long)NN * DD);
}

// round 14
// speedup vs baseline: 1.0867x; 1.0867x over previous
#include <cuda_runtime.h>
#include <cuda_fp16.h>
#include <cstdint>
#include <math.h>

#define BB 4
#define NN 4096
#define DD 512

// ---------------- device scratch (allocation-free rule) ----------------
__device__ __half g_Eh[(size_t)BB * NN * NN];   // 134 MB, fp16
__device__ __half g_xh[(size_t)BB * NN * DD];
__device__ __half g_wth[DD * DD];               // w^T fp16
__device__ __half g_yth[(size_t)BB * DD * NN];  // y^T fp16 (B-operand layout)
__device__ float  g_s [BB * NN];
__device__ float  g_v [DD];                     // v = w @ a

// ---------------- PTX helpers ----------------
__device__ __forceinline__ uint32_t smem_u32(const void* p) {
    uint32_t a;
    asm("{ .reg .u64 t; cvta.to.shared.u64 t, %1; cvt.u32.u64 %0, t; }" : "=r"(a) : "l"(p));
    return a;
}
__device__ __forceinline__ void cp16(uint32_t smem_addr, const void* gptr) {
    asm volatile("cp.async.cg.shared.global [%0], [%1], 16;" :: "r"(smem_addr), "l"(gptr));
}
#define CP_COMMIT() asm volatile("cp.async.commit_group;" ::: "memory")
template <int N> __device__ __forceinline__ void cp_wait() {
    asm volatile("cp.async.wait_group %0;" :: "n"(N) : "memory");
}
__device__ __forceinline__ void ldsm4(uint32_t& r0, uint32_t& r1, uint32_t& r2, uint32_t& r3,
                                      uint32_t addr) {
    asm volatile("ldmatrix.sync.aligned.m8n8.x4.shared.b16 {%0,%1,%2,%3}, [%4];"
                 : "=r"(r0), "=r"(r1), "=r"(r2), "=r"(r3) : "r"(addr));
}
__device__ __forceinline__ void mma16816(float* c, const uint32_t* a, const uint32_t* b) {
    asm volatile(
        "mma.sync.aligned.m16n8k16.row.col.f32.f16.f16.f32 "
        "{%0,%1,%2,%3}, {%4,%5,%6,%7}, {%8,%9}, {%0,%1,%2,%3};"
        : "+f"(c[0]), "+f"(c[1]), "+f"(c[2]), "+f"(c[3])
        : "r"(a[0]), "r"(a[1]), "r"(a[2]), "r"(a[3]), "r"(b[0]), "r"(b[1]));
}

// ================= GEMM: C[M,N] = A[M,K] @ B[N,K]^T, fp16 1-MMA =================
// CTA 128x128, 128 threads (4 warps), warp tile 64x64, BK=64, 3 stages, 2 CTAs/SM.
#define ROWB 144
#define ABYTES (128 * ROWB)                  // 18432 per matrix tile
#define MSTAGES 3
#define MSTAGE_BYTES (2 * ABYTES)            // 36864
#define GEMM_SMEM (MSTAGES * MSTAGE_BYTES)   // 110592

template <typename OutT>
__global__ void __launch_bounds__(128, 2) gemm_f16(
    const __half* __restrict__ A_, const __half* __restrict__ B_,
    OutT* __restrict__ C_,
    int K, int lda, int ldb, int ldc,
    long long sAz, long long sBz, long long sCz)
{
    extern __shared__ char smem[];
    const uint32_t sb = smem_u32(smem);
    const int tid  = threadIdx.x;
    const int wid  = tid >> 5;
    const int lane = tid & 31;
    const int bcol = blockIdx.x * 128;
    const int brow = blockIdx.y * 128;
    const __half* A = A_ + (size_t)blockIdx.z * sAz;
    const __half* B = B_ + (size_t)blockIdx.z * sBz;
    OutT* C = C_ + (size_t)blockIdx.z * sCz;

    const int m_base = (wid & 1) * 64;
    const int n_base = (wid >> 1) * 64;

    float acc[4][8][4];
#pragma unroll
    for (int t = 0; t < 4; t++)
#pragma unroll
        for (int n = 0; n < 8; n++)
#pragma unroll
            for (int j = 0; j < 4; j++) acc[t][n][j] = 0.f;

    const int NCH = K >> 6;                   // K chunks of 64

    auto load_chunk = [&](int c, int s) {
        const int k0 = c << 6;
        const uint32_t base = sb + s * MSTAGE_BYTES;
#pragma unroll
        for (int i = 0; i < 8; i++) {
            int id = tid + (i << 7);          // 0..1023
            int r  = id >> 3;                 // row 0..127
            int ch = id & 7;                  // 16B chunk 0..7
            uint32_t so = r * ROWB + ch * 16;
            cp16(base + so,          A + (size_t)(brow + r) * lda + k0 + ch * 8);
            cp16(base + ABYTES + so, B + (size_t)(bcol + r) * ldb + k0 + ch * 8);
        }
    };

    const uint32_t aoff = (uint32_t)(m_base + (lane & 15)) * ROWB + (lane >> 4) * 16;
    const uint32_t boff = (uint32_t)(n_base + (lane & 7) + ((lane >> 4) << 3)) * ROWB
                        + ((lane >> 3) & 1) * 16;

    auto compute = [&](int s) {
        const uint32_t base = sb + s * MSTAGE_BYTES;
#pragma unroll
        for (int kk = 0; kk < 4; kk++) {
            const uint32_t kb = kk * 32;
            uint32_t af[4][4], bf[4][4];
#pragma unroll
            for (int t = 0; t < 4; t++)
                ldsm4(af[t][0], af[t][1], af[t][2], af[t][3],
                      base + aoff + (uint32_t)t * (16 * ROWB) + kb);
#pragma unroll
            for (int p = 0; p < 4; p++)
                ldsm4(bf[p][0], bf[p][1], bf[p][2], bf[p][3],
                      base + ABYTES + boff + (uint32_t)p * (16 * ROWB) + kb);
#pragma unroll
            for (int t = 0; t < 4; t++)
#pragma unroll
                for (int n = 0; n < 8; n++)
                    mma16816(acc[t][n], af[t], &bf[n >> 1][(n & 1) * 2]);
        }
    };

#pragma unroll
    for (int p = 0; p < MSTAGES - 1; p++) {
        if (p < NCH) load_chunk(p, p);
        CP_COMMIT();
    }
    for (int c = 0; c < NCH; c++) {
        cp_wait<MSTAGES - 2>();
        __syncthreads();
        if (c + MSTAGES - 1 < NCH) load_chunk(c + MSTAGES - 1, (c + MSTAGES - 1) % MSTAGES);
        CP_COMMIT();
        compute(c % MSTAGES);
    }

#pragma unroll
    for (int t = 0; t < 4; t++) {
        const int m0 = brow + m_base + t * 16 + (lane >> 2);
#pragma unroll
        for (int n = 0; n < 8; n++) {
            const int cn = bcol + n_base + n * 8 + (lane & 3) * 2;
            if constexpr (sizeof(OutT) == 4) {
                *(float2*)((float*)C + (size_t)m0 * ldc + cn) =
                    make_float2(acc[t][n][0], acc[t][n][1]);
                *(float2*)((float*)C + (size_t)(m0 + 8) * ldc + cn) =
                    make_float2(acc[t][n][2], acc[t][n][3]);
            } else {
                __half2 h0 = __floats2half2_rn(acc[t][n][0], acc[t][n][1]);
                __half2 h1 = __floats2half2_rn(acc[t][n][2], acc[t][n][3]);
                *(__half2*)((__half*)C + (size_t)m0 * ldc + cn)       = h0;
                *(__half2*)((__half*)C + (size_t)(m0 + 8) * ldc + cn) = h1;
            }
        }
    }
}

// ---------------- small kernels ----------------
__global__ void __launch_bounds__(128) split_s_k(const float* __restrict__ x) {
    const int row = blockIdx.x;
    float4 xv = ((const float4*)(x + (size_t)row * DD))[threadIdx.x];
    float4 vv = ((const float4*)g_v)[threadIdx.x];
    __half2 h01 = __floats2half2_rn(xv.x, xv.y);
    __half2 h23 = __floats2half2_rn(xv.z, xv.w);
    *(uint2*)(g_xh + (size_t)row * DD + threadIdx.x * 4) =
        make_uint2(*(uint32_t*)&h01, *(uint32_t*)&h23);
    float sum = xv.x * vv.x + xv.y * vv.y + xv.z * vv.z + xv.w * vv.w;
#pragma unroll
    for (int o = 16; o; o >>= 1) sum += __shfl_xor_sync(0xffffffffu, sum, o);
    __shared__ float red[4];
    if ((threadIdx.x & 31) == 0) red[threadIdx.x >> 5] = sum;
    __syncthreads();
    if (threadIdx.x == 0) g_s[row] = red[0] + red[1] + red[2] + red[3];
}

__global__ void __launch_bounds__(256) wt_k(const float* __restrict__ w) {
    int id = blockIdx.x * 256 + threadIdx.x;   // id = n*512 + k
    int n = id >> 9, k = id & 511;
    g_wth[id] = __float2half(w[k * DD + n]);
}

__global__ void __launch_bounds__(128) v_k(const float* __restrict__ w, const float* __restrict__ a) {
    int k = blockIdx.x;
    float sum = 0.f;
    for (int t = threadIdx.x; t < DD; t += 128) sum += w[k * DD + t] * a[t];
#pragma unroll
    for (int o = 16; o; o >>= 1) sum += __shfl_xor_sync(0xffffffffu, sum, o);
    __shared__ float red[4];
    if ((threadIdx.x & 31) == 0) red[threadIdx.x >> 5] = sum;
    __syncthreads();
    if (threadIdx.x == 0) g_v[k] = red[0] + red[1] + red[2] + red[3];
}

// Register-resident row pass: 128 threads, 32 E-values/thread in regs,
// <=64 regs (launch_bounds min 8 blocks), ~0 smem -> co-resides with GEMM CTAs.
__global__ void __launch_bounds__(128, 8) row_kernel(const float* __restrict__ A_shape, int base) {
    const int row = base + blockIdx.x;      // b*NN + i
    const int b   = row >> 12;
    const float4* arow4 = (const float4*)(A_shape + (size_t)row * NN);
    const float4* srow4 = (const float4*)(g_s + (size_t)b * NN);
    const float  si   = g_s[row];

    float e[8][4];
    float deg = 0.f, R = 0.f;

#pragma unroll
    for (int q = 0; q < 8; q++) {
        int j4 = threadIdx.x + q * 128;
        float4 av = arow4[j4];
        float4 sv = srow4[j4];
        float aa[4] = {av.x, av.y, av.z, av.w};
        float ss[4] = {sv.x, sv.y, sv.z, sv.w};
#pragma unroll
        for (int k = 0; k < 4; k++) {
            float u  = (si + ss[k]) * 0.125f;
            float eu = __expf(-2.f * fabsf(u));
            float tt = __fdividef(1.f - eu, 1.f + eu);
            tt = copysignf(tt, u);
            float Av = 8.f * tt;
            Av = (Av >= 0.f) ? Av : 0.1f * Av;
            e[q][k] = __expf(Av) * aa[k];
            deg += aa[k]; R += e[q][k];
        }
    }
#pragma unroll
    for (int o = 16; o; o >>= 1) {
        deg += __shfl_xor_sync(0xffffffffu, deg, o);
        R   += __shfl_xor_sync(0xffffffffu, R, o);
    }
    __shared__ float wdeg[4], wR[4], s_scale;
    const int warp = threadIdx.x >> 5;
    if ((threadIdx.x & 31) == 0) { wdeg[warp] = deg; wR[warp] = R; }
    __syncthreads();
    if (threadIdx.x == 0)
        s_scale = (wdeg[0] + wdeg[1] + wdeg[2] + wdeg[3]) /
                  (wR[0] + wR[1] + wR[2] + wR[3]);
    __syncthreads();
    const float sc = s_scale;

    __half* eh = g_Eh + (size_t)row * NN;
#pragma unroll
    for (int q = 0; q < 8; q++) {
        int j4 = threadIdx.x + q * 128;
        __half2 h01 = __floats2half2_rn(e[q][0] * sc, e[q][1] * sc);
        __half2 h23 = __floats2half2_rn(e[q][2] * sc, e[q][3] * sc);
        *(uint2*)(eh + j4 * 4) = make_uint2(*(uint32_t*)&h01, *(uint32_t*)&h23);
    }
}

// ---------------- launch ----------------
extern "C" void kernel_launch(void* const* d_in, const int* in_sizes, int n_in,
                              void* d_out, int out_size)
{
    const float* x       = (const float*)d_in[0];
    const float* A_shape = (const float*)d_in[1];
    const float* w       = (const float*)d_in[2];
    const float* a       = (const float*)d_in[3];
    float* out = (float*)d_out;

    __half *pxh, *pwth, *pyth, *pEh;
    cudaGetSymbolAddress((void**)&pxh,  g_xh);
    cudaGetSymbolAddress((void**)&pwth, g_wth);
    cudaGetSymbolAddress((void**)&pyth, g_yth);
    cudaGetSymbolAddress((void**)&pEh,  g_Eh);

    cudaFuncSetAttribute(gemm_f16<float>,  cudaFuncAttributeMaxDynamicSharedMemorySize, GEMM_SMEM);
    cudaFuncSetAttribute(gemm_f16<__half>, cudaFuncAttributeMaxDynamicSharedMemorySize, GEMM_SMEM);

    // ONE extra stream (empirically passes the allocation guard; 4 did not)
    static cudaStream_t sR = nullptr;
    static cudaEvent_t evSplit = nullptr, evY = nullptr, evRow1 = nullptr, evG23 = nullptr;
    if (sR == nullptr) {
        cudaStreamCreateWithFlags(&sR, cudaStreamNonBlocking);
        cudaEventCreateWithFlags(&evSplit, cudaEventDisableTiming);
        cudaEventCreateWithFlags(&evY, cudaEventDisableTiming);
        cudaEventCreateWithFlags(&evRow1, cudaEventDisableTiming);
        cudaEventCreateWithFlags(&evG23, cudaEventDisableTiming);
    }

    wt_k<<<(DD * DD) / 256, 256>>>(w);
    v_k<<<DD, 128>>>(w, a);
    split_s_k<<<BB * NN, 128>>>(x);
    cudaEventRecord(evSplit, 0);

    // side stream: rows b0,b1 -> evRow1 -> rows b2,b3 -> (wait y) gemm(2,3)
    cudaStreamWaitEvent(sR, evSplit, 0);
    row_kernel<<<NN, 128, 0, sR>>>(A_shape, 0 * NN);
    row_kernel<<<NN, 128, 0, sR>>>(A_shape, 1 * NN);
    cudaEventRecord(evRow1, sR);
    row_kernel<<<NN, 128, 0, sR>>>(A_shape, 2 * NN);
    row_kernel<<<NN, 128, 0, sR>>>(A_shape, 3 * NN);

    // main stream: y^T = wt @ x^T (all batches)
    gemm_f16<__half><<<dim3(NN / 128, DD / 128, BB), 128, GEMM_SMEM>>>(
        pwth, pxh, pyth,
        DD, DD, DD, NN,
        0, (long long)NN * DD, (long long)DD * NN);
    cudaEventRecord(evY, 0);

    // side stream: gemm for batches 2,3 (after its rows + y^T)
    cudaStreamWaitEvent(sR, evY, 0);
    gemm_f16<float><<<dim3(DD / 128, NN / 128, 2), 128, GEMM_SMEM, sR>>>(
        pEh + (size_t)2 * NN * NN,
        pyth + (size_t)2 * DD * NN,
        out + (size_t)2 * NN * DD,
        NN, NN, NN, DD,
        (long long)NN * NN, (long long)DD * NN, (long long)NN * DD);
    cudaEventRecord(evG23, sR);

    // main stream: gemm for batches 0,1 (after rows b0,b1; y^T already ordered)
    cudaStreamWaitEvent(0, evRow1, 0);
    gemm_f16<float><<<dim3(DD / 128, NN / 128, 2), 128, GEMM_SMEM>>>(
        pEh, pyth, out,
        NN, NN, NN, DD,
        (long long)NN * NN, (long long)DD * NN, (long long)NN * DD);

    // join
    cudaStreamWaitEvent(0, evG23, 0);
}